// round 1
// baseline (speedup 1.0000x reference)
#include <cuda_runtime.h>

#define Bq 4
#define Sq 1024
#define Eq 1024
#define Hq 16
#define HDq 64
#define Mtot (Bq*Sq)   // 4096

// Scratch (static device globals: allocation-free)
__device__ float g_Q[Bq*Hq*Sq*HDq];    // [B,H,S,HD]
__device__ float g_K[Bq*Hq*Sq*HDq];
__device__ float g_V[Bq*Hq*Sq*HDq];
__device__ float g_ctx[Bq*Sq*Eq];      // [B,S,E] (concat layout)

// ---------------------------------------------------------------------------
// NT SGEMM: C[M,N] = A[M,K] @ W[N,K]^T, K = N = 1024, M = 4096.
// 128x128 block tile, kstep 8, 256 threads, 8x8 per-thread micro-tile.
// remap=1: scatter C into [B,H,S,HD] layout (for Q/K/V projections).
// remap=0: plain row-major [M,N] store (output projection).
// ---------------------------------------------------------------------------
__global__ void __launch_bounds__(256, 2)
gemm_nt(const float* __restrict__ A, const float* __restrict__ W,
        float* __restrict__ C, int remap, float scale)
{
    __shared__ float As[8][128];
    __shared__ float Bs[8][128];
    const int K = Eq;
    const int t  = threadIdx.x;
    const int tx = t & 15, ty = t >> 4;
    const int arow = t >> 1;          // 0..127
    const int ac4  = (t & 1) * 4;     // 0 or 4

    const float* Ap = A + (size_t)(blockIdx.y * 128 + arow) * K + ac4;
    const float* Wp = W + (size_t)(blockIdx.x * 128 + arow) * K + ac4;

    float acc[8][8];
#pragma unroll
    for (int i = 0; i < 8; ++i)
#pragma unroll
        for (int j = 0; j < 8; ++j) acc[i][j] = 0.f;

    for (int kt = 0; kt < K; kt += 8) {
        float4 av = *(const float4*)(Ap + kt);
        float4 wv = *(const float4*)(Wp + kt);
        __syncthreads();   // previous compute done before smem overwrite
        As[ac4+0][arow] = av.x; As[ac4+1][arow] = av.y;
        As[ac4+2][arow] = av.z; As[ac4+3][arow] = av.w;
        Bs[ac4+0][arow] = wv.x; Bs[ac4+1][arow] = wv.y;
        Bs[ac4+2][arow] = wv.z; Bs[ac4+3][arow] = wv.w;
        __syncthreads();
#pragma unroll
        for (int c = 0; c < 8; ++c) {
            float4 a0 = *(const float4*)&As[c][ty*8];
            float4 a1 = *(const float4*)&As[c][ty*8+4];
            float4 b0 = *(const float4*)&Bs[c][tx*8];
            float4 b1 = *(const float4*)&Bs[c][tx*8+4];
            float a[8] = {a0.x,a0.y,a0.z,a0.w,a1.x,a1.y,a1.z,a1.w};
            float b[8] = {b0.x,b0.y,b0.z,b0.w,b1.x,b1.y,b1.z,b1.w};
#pragma unroll
            for (int i = 0; i < 8; ++i)
#pragma unroll
                for (int j = 0; j < 8; ++j)
                    acc[i][j] = fmaf(a[i], b[j], acc[i][j]);
        }
    }

    if (remap == 0) {
#pragma unroll
        for (int i = 0; i < 8; ++i) {
            size_t m = (size_t)blockIdx.y * 128 + ty*8 + i;
            float* dst = C + m * Eq + blockIdx.x * 128 + tx*8;
            float4 o0 = make_float4(acc[i][0]*scale, acc[i][1]*scale,
                                    acc[i][2]*scale, acc[i][3]*scale);
            float4 o1 = make_float4(acc[i][4]*scale, acc[i][5]*scale,
                                    acc[i][6]*scale, acc[i][7]*scale);
            *(float4*)(dst)     = o0;
            *(float4*)(dst + 4) = o1;
        }
    } else {
        // n -> (h, d); m -> (b, s); dst layout [B,H,S,HD]
        const int n0 = blockIdx.x * 128 + tx*8;
        const int h  = n0 >> 6;
        const int d  = n0 & 63;   // span of 8 stays inside one head (64 % 8 == 0)
#pragma unroll
        for (int i = 0; i < 8; ++i) {
            int m = blockIdx.y * 128 + ty*8 + i;
            int b = m >> 10, s = m & 1023;
            float* dst = C + (((size_t)(b*Hq + h))*Sq + s)*HDq + d;
            float4 o0 = make_float4(acc[i][0]*scale, acc[i][1]*scale,
                                    acc[i][2]*scale, acc[i][3]*scale);
            float4 o1 = make_float4(acc[i][4]*scale, acc[i][5]*scale,
                                    acc[i][6]*scale, acc[i][7]*scale);
            *(float4*)(dst)     = o0;
            *(float4*)(dst + 4) = o1;
        }
    }
}

// ---------------------------------------------------------------------------
// Flash-style attention: one block per (q-tile of 64, head, batch).
// 256 threads as 16 groups x 16 lanes; each thread owns a 4x4 micro-tile.
// Online softmax; P staged in smem; output written in concat layout [B,S,E].
// Scale already folded into Q at projection time.
// ---------------------------------------------------------------------------
#define KPAD 68
#define ATTN_SMEM ((64*64*3 + 64*KPAD) * 4)   // Qs + Vs + Ps (stride 64) + Ks (stride 68)

__global__ void __launch_bounds__(256)
attn_kernel(const float* __restrict__ Q, const float* __restrict__ Kg,
            const float* __restrict__ Vg, float* __restrict__ ctx)
{
    extern __shared__ float smp[];
    float* Qs = smp;              // [64][64]
    float* Ks = Qs + 64*64;       // [64][KPAD]
    float* Vs = Ks + 64*KPAD;     // [64][64]
    float* Ps = Vs + 64*64;       // [64][64]

    const int t  = threadIdx.x;
    const int tx = t & 15;
    const int r0 = (t >> 4) * 4;  // 4 query rows owned by this thread's group
    const int c0 = tx * 4;        // 4 kv cols / 4 head-dims owned by this thread
    const int qb = blockIdx.x, h = blockIdx.y, b = blockIdx.z;

    const float* Qgp = Q  + (((size_t)(b*Hq + h))*Sq + qb*64) * HDq;
    const float* Kgp = Kg + ((size_t)(b*Hq + h))*Sq*HDq;
    const float* Vgp = Vg + ((size_t)(b*Hq + h))*Sq*HDq;

#pragma unroll
    for (int i = t; i < 1024; i += 256)
        ((float4*)Qs)[i] = ((const float4*)Qgp)[i];

    float acc[4][4] = {};
    float mI[4], lI[4];
#pragma unroll
    for (int i = 0; i < 4; ++i) { mI[i] = -1e30f; lI[i] = 0.f; }

    for (int kt = 0; kt < 16; ++kt) {
        __syncthreads();   // previous tile's PV done before K/V overwrite
        const float4* Kt = (const float4*)(Kgp + (size_t)kt*64*64);
        const float4* Vt = (const float4*)(Vgp + (size_t)kt*64*64);
#pragma unroll
        for (int i = t; i < 1024; i += 256) {
            float4 kv = Kt[i];
            int r = i >> 4, cc = (i & 15) << 2;
            *(float4*)(Ks + r*KPAD + cc) = kv;
            ((float4*)Vs)[i] = Vt[i];
        }
        __syncthreads();

        // S = Q @ K^T for this 64x64 tile
        float sc[4][4] = {};
#pragma unroll
        for (int dc = 0; dc < 64; dc += 4) {
            float4 q4[4], k4[4];
#pragma unroll
            for (int i = 0; i < 4; ++i) q4[i] = *(const float4*)(Qs + (r0+i)*64 + dc);
#pragma unroll
            for (int j = 0; j < 4; ++j) k4[j] = *(const float4*)(Ks + (c0+j)*KPAD + dc);
#pragma unroll
            for (int i = 0; i < 4; ++i)
#pragma unroll
                for (int j = 0; j < 4; ++j) {
                    sc[i][j] = fmaf(q4[i].x, k4[j].x, sc[i][j]);
                    sc[i][j] = fmaf(q4[i].y, k4[j].y, sc[i][j]);
                    sc[i][j] = fmaf(q4[i].z, k4[j].z, sc[i][j]);
                    sc[i][j] = fmaf(q4[i].w, k4[j].w, sc[i][j]);
                }
        }

        // Online softmax (row reductions across the 16 lanes of this group)
#pragma unroll
        for (int i = 0; i < 4; ++i) {
            float rm = fmaxf(fmaxf(sc[i][0], sc[i][1]), fmaxf(sc[i][2], sc[i][3]));
#pragma unroll
            for (int off = 8; off; off >>= 1)
                rm = fmaxf(rm, __shfl_xor_sync(0xffffffffu, rm, off, 16));
            float mn    = fmaxf(mI[i], rm);
            float alpha = __expf(mI[i] - mn);
            mI[i] = mn;
            float rs = 0.f;
#pragma unroll
            for (int j = 0; j < 4; ++j) { sc[i][j] = __expf(sc[i][j] - mn); rs += sc[i][j]; }
#pragma unroll
            for (int off = 8; off; off >>= 1)
                rs += __shfl_xor_sync(0xffffffffu, rs, off, 16);
            lI[i] = lI[i]*alpha + rs;
#pragma unroll
            for (int j = 0; j < 4; ++j) acc[i][j] *= alpha;
            *(float4*)(Ps + (r0+i)*64 + c0) =
                make_float4(sc[i][0], sc[i][1], sc[i][2], sc[i][3]);
        }
        __syncthreads();

        // O += P @ V  (this thread accumulates rows r0..r0+3, head-dims c0..c0+3)
#pragma unroll 8
        for (int j = 0; j < 64; ++j) {
            float4 v4 = *(const float4*)(Vs + j*64 + c0);
            float p0 = Ps[(r0+0)*64 + j];
            float p1 = Ps[(r0+1)*64 + j];
            float p2 = Ps[(r0+2)*64 + j];
            float p3 = Ps[(r0+3)*64 + j];
            acc[0][0] = fmaf(p0, v4.x, acc[0][0]); acc[0][1] = fmaf(p0, v4.y, acc[0][1]);
            acc[0][2] = fmaf(p0, v4.z, acc[0][2]); acc[0][3] = fmaf(p0, v4.w, acc[0][3]);
            acc[1][0] = fmaf(p1, v4.x, acc[1][0]); acc[1][1] = fmaf(p1, v4.y, acc[1][1]);
            acc[1][2] = fmaf(p1, v4.z, acc[1][2]); acc[1][3] = fmaf(p1, v4.w, acc[1][3]);
            acc[2][0] = fmaf(p2, v4.x, acc[2][0]); acc[2][1] = fmaf(p2, v4.y, acc[2][1]);
            acc[2][2] = fmaf(p2, v4.z, acc[2][2]); acc[2][3] = fmaf(p2, v4.w, acc[2][3]);
            acc[3][0] = fmaf(p3, v4.x, acc[3][0]); acc[3][1] = fmaf(p3, v4.y, acc[3][1]);
            acc[3][2] = fmaf(p3, v4.z, acc[3][2]); acc[3][3] = fmaf(p3, v4.w, acc[3][3]);
        }
    }

    // Normalize and write concat layout [B, S, E], e = h*64 + d
#pragma unroll
    for (int i = 0; i < 4; ++i) {
        float inv = 1.0f / lI[i];
        float* dst = ctx + ((size_t)b*Sq + qb*64 + r0 + i)*Eq + h*64 + c0;
        *(float4*)dst = make_float4(acc[i][0]*inv, acc[i][1]*inv,
                                    acc[i][2]*inv, acc[i][3]*inv);
    }
}

// ---------------------------------------------------------------------------
extern "C" void kernel_launch(void* const* d_in, const int* in_sizes, int n_in,
                              void* d_out, int out_size)
{
    const float* q  = (const float*)d_in[0];
    const float* k  = (const float*)d_in[1];
    const float* v  = (const float*)d_in[2];
    const float* Wq = (const float*)d_in[3];
    const float* Wk = (const float*)d_in[4];
    const float* Wv = (const float*)d_in[5];
    const float* Wo = (const float*)d_in[6];
    float* out = (float*)d_out;

    float *gQ, *gK, *gV, *gctx;
    cudaGetSymbolAddress((void**)&gQ,   g_Q);
    cudaGetSymbolAddress((void**)&gK,   g_K);
    cudaGetSymbolAddress((void**)&gV,   g_V);
    cudaGetSymbolAddress((void**)&gctx, g_ctx);

    dim3 ggrid(Eq/128, Mtot/128);   // (8, 32)

    // Projections (softmax scale 1/sqrt(64) folded into Q)
    gemm_nt<<<ggrid, 256>>>(q, Wq, gQ, 1, 0.125f);
    gemm_nt<<<ggrid, 256>>>(k, Wk, gK, 1, 1.0f);
    gemm_nt<<<ggrid, 256>>>(v, Wv, gV, 1, 1.0f);

    // Attention
    cudaFuncSetAttribute(attn_kernel, cudaFuncAttributeMaxDynamicSharedMemorySize,
                         ATTN_SMEM);
    attn_kernel<<<dim3(Sq/64, Hq, Bq), 256, ATTN_SMEM>>>(gQ, gK, gV, gctx);

    // Output projection straight into d_out
    gemm_nt<<<ggrid, 256>>>(gctx, Wo, out, 0, 1.0f);
}